// round 6
// baseline (speedup 1.0000x reference)
#include <cuda_runtime.h>
#include <cstdint>

// y[16,8192] = x[16,8192] @ (W[8192,8192] * scale[o, k/128])^T + bias
#define BATCH 16
#define INF   8192
#define OUTF  8192
#define NG    64
#define GRP   128
#define THREADS 256
#define ROWS_PER_BLOCK 32
#define NBLOCKS (OUTF / ROWS_PER_BLOCK)   // 256
#define PF 5                               // W cp.async pipeline stages
#define WSTG 4096                          // floats per W stage (32 rows * 128)
#define XSTG 2048                          // floats per x group buffer (16 * 128)
// smem: ws[PF][4096] | xs[2][2048] | ss[2048]
#define SMEM_FLOATS (PF * WSTG + 2 * XSTG + ROWS_PER_BLOCK * NG)
#define SMEM_BYTES  (SMEM_FLOATS * 4)      // 106496

__device__ __forceinline__ unsigned long long fma2(unsigned long long a,
                                                   unsigned long long b,
                                                   unsigned long long c) {
    unsigned long long d;
    asm("fma.rn.f32x2 %0, %1, %2, %3;" : "=l"(d) : "l"(a), "l"(b), "l"(c));
    return d;
}
__device__ __forceinline__ unsigned long long add2(unsigned long long a,
                                                   unsigned long long b) {
    unsigned long long d;
    asm("add.rn.f32x2 %0, %1, %2;" : "=l"(d) : "l"(a), "l"(b));
    return d;
}
__device__ __forceinline__ unsigned long long pack2(float lo, float hi) {
    unsigned long long d;
    asm("mov.b64 %0, {%1, %2};" : "=l"(d) : "f"(lo), "f"(hi));
    return d;
}
__device__ __forceinline__ float2 unpack2(unsigned long long v) {
    float2 r;
    asm("mov.b64 {%0, %1}, %2;" : "=f"(r.x), "=f"(r.y) : "l"(v));
    return r;
}
__device__ __forceinline__ void cp16(uint32_t dst_smem, const void* src) {
    asm volatile("cp.async.cg.shared.global [%0], [%1], 16;"
                 :: "r"(dst_smem), "l"(src));
}

extern __shared__ float smem[];

// W stage: cp.async 16KB (32 rows x 512B) for group g into stage slot.
__device__ __forceinline__ void issue_w(uint32_t smem_u32, const float* __restrict__ w,
                                        int g, int slot, int tid, int row_base)
{
    #pragma unroll
    for (int j = 0; j < 4; ++j) {
        int uid = tid + j * THREADS;
        int row = uid >> 5;
        int un  = uid & 31;
        cp16(smem_u32 + (uint32_t)((slot * WSTG + row * GRP + un * 4) * 4),
             w + (size_t)(row_base + row) * INF + (size_t)g * GRP + un * 4);
    }
}

// x stage (transposed + swizzled): buf[region=i*4+u][slot=q^(2i)][4 floats]
// holds x[batch 4u+c][k = 4q + i].  Reader lane L uses slot L^(2i).
// Writer STS.128 and reader LDS.128 are both bank-conflict-free.
__device__ __forceinline__ void stage_x(float* buf, const float* __restrict__ x,
                                        int g, int tid)
{
    #pragma unroll
    for (int j = 0; j < 2; ++j) {
        int uid  = tid + j * THREADS;      // 0..511
        int u    = uid >> 7;               // batch quad 0..3
        int kloc = uid & 127;              // k within group (coalesced over tid)
        int i    = kloc & 3;
        int q    = kloc >> 2;
        const float* xp = x + (size_t)g * GRP + kloc;
        float4 v;
        v.x = xp[(size_t)(4 * u + 0) * INF];
        v.y = xp[(size_t)(4 * u + 1) * INF];
        v.z = xp[(size_t)(4 * u + 2) * INF];
        v.w = xp[(size_t)(4 * u + 3) * INF];
        int slot = q ^ (i << 1);
        *(float4*)(buf + (i * 4 + u) * 128 + slot * 4) = v;
    }
}

__global__ void __launch_bounds__(THREADS, 2)
dsew_linear_kernel(const float* __restrict__ x,
                   const float* __restrict__ w,
                   const float* __restrict__ scale,
                   const float* __restrict__ bias,
                   float* __restrict__ out)
{
    float* ws = smem;                       // [PF][WSTG]
    float* xs = smem + PF * WSTG;           // [2][XSTG]
    float* ss = xs + 2 * XSTG;              // [32][NG]

    const int tid    = threadIdx.x;
    const int warp   = tid >> 5;
    const int lane   = tid & 31;
    const int rowgrp = warp >> 1;           // 0..3 -> rows rowgrp*8 .. +7
    const int h      = warp & 1;            // batch half: batches 8h..8h+7
    const int row_base = blockIdx.x * ROWS_PER_BLOCK;

    const uint32_t smem_u32 = (uint32_t)__cvta_generic_to_shared(smem);

    // stage scales [32][64] (contiguous in global)
    for (int i = tid; i < ROWS_PER_BLOCK * NG; i += THREADS)
        ss[i] = scale[(size_t)row_base * NG + i];

    // prologue: W stages 0..PF-2, x group 0
    #pragma unroll
    for (int s = 0; s < PF - 1; ++s) {
        issue_w(smem_u32, w, s, s, tid, row_base);
        asm volatile("cp.async.commit_group;");
    }
    stage_x(xs, x, 0, tid);
    __syncthreads();

    // accumulators: acc[r][bp] = f32x2 over batches (8h+2bp, 8h+2bp+1), row rowgrp*8+r
    unsigned long long acc[8][4];
    #pragma unroll
    for (int r = 0; r < 8; ++r)
        #pragma unroll
        for (int p = 0; p < 4; ++p) acc[r][p] = 0ull;

    const int srow = rowgrp * 8;

    #pragma unroll 1
    for (int g = 0; g < NG; ++g) {
        asm volatile("cp.async.wait_group %0;" :: "n"(PF - 2));
        __syncthreads();

        if (g + PF - 1 < NG)
            issue_w(smem_u32, w, g + PF - 1, (g + PF - 1) % PF, tid, row_base);
        asm volatile("cp.async.commit_group;");

        if (g + 1 < NG)
            stage_x(xs + ((g + 1) & 1) * XSTG, x, g + 1, tid);

        const float* wg = ws + (g % PF) * WSTG + srow * GRP;
        const float* xg = xs + (g & 1) * XSTG;

        float s[8];
        #pragma unroll
        for (int r = 0; r < 8; ++r) s[r] = ss[(srow + r) * NG + g];

        #pragma unroll
        for (int ih = 0; ih < 2; ++ih) {
            // W: k = 4*lane + {2ih, 2ih+1} for each of this warp's 8 rows
            float2 wr[8];
            #pragma unroll
            for (int r = 0; r < 8; ++r)
                wr[r] = *(const float2*)(wg + r * GRP + lane * 4 + ih * 2);

            #pragma unroll
            for (int ii = 0; ii < 2; ++ii) {
                const int i = ih * 2 + ii;
                unsigned long long w2[8];
                #pragma unroll
                for (int r = 0; r < 8; ++r) {
                    float f = (ii ? wr[r].y : wr[r].x) * s[r];
                    w2[r] = pack2(f, f);
                }
                const int soff = (lane ^ (i << 1)) * 4;
                ulonglong2 xv0 = *(const ulonglong2*)(xg + (i * 4 + 2 * h)     * 128 + soff);
                ulonglong2 xv1 = *(const ulonglong2*)(xg + (i * 4 + 2 * h + 1) * 128 + soff);
                #pragma unroll
                for (int r = 0; r < 8; ++r) {
                    acc[r][0] = fma2(xv0.x, w2[r], acc[r][0]);
                    acc[r][1] = fma2(xv0.y, w2[r], acc[r][1]);
                    acc[r][2] = fma2(xv1.x, w2[r], acc[r][2]);
                    acc[r][3] = fma2(xv1.y, w2[r], acc[r][3]);
                }
            }
        }
    }

    // epilogue: reduce over the 32 k-lanes, add bias, scatter
    #pragma unroll
    for (int r = 0; r < 8; ++r) {
        const int row = row_base + srow + r;
        const float bi = bias[row];
        #pragma unroll
        for (int p = 0; p < 4; ++p) {
            unsigned long long v = acc[r][p];
            #pragma unroll
            for (int off = 16; off; off >>= 1)
                v = add2(v, __shfl_xor_sync(0xffffffffu, v, off));
            if (lane == 0) {
                float2 f = unpack2(v);
                const int b = 8 * h + 2 * p;
                out[(size_t)b       * OUTF + row] = f.x + bi;
                out[(size_t)(b + 1) * OUTF + row] = f.y + bi;
            }
        }
    }
}

extern "C" void kernel_launch(void* const* d_in, const int* in_sizes, int n_in,
                              void* d_out, int out_size)
{
    const float* x     = (const float*)d_in[0]; // [16, 8192]
    const float* wgt   = (const float*)d_in[1]; // [8192, 8192]
    const float* scale = (const float*)d_in[2]; // [8192, 64]
    const float* bias  = (const float*)d_in[3]; // [1, 8192]
    // d_in[4] (types) has no effect on the reference math.
    float* out = (float*)d_out;                 // [16, 8192]

    cudaFuncSetAttribute(dsew_linear_kernel,
                         cudaFuncAttributeMaxDynamicSharedMemorySize, SMEM_BYTES);
    dsew_linear_kernel<<<NBLOCKS, THREADS, SMEM_BYTES>>>(x, wgt, scale, bias, out);
}